// round 4
// baseline (speedup 1.0000x reference)
#include <cuda_runtime.h>
#include <math.h>
#include <stdint.h>

// ---------------- problem dims ----------------
// T=32 B=16 D=512 H=512 E=512 C=512 FH=8 FW=32, HW=256
// out: (B, T, H+E) = (16, 32, 1024) float32

// ---------------- device scratch ----------------
__device__ float g_hT[2][2 * 512 * 16];     // h state, double-buffered: [phase][dir*8192 + h*16 + b]
__device__ float g_cT[2 * 512 * 16];        // c state [dir][h][b]
__device__ float g_hseq[512 * 1024];        // (t*16+b, [fwd 512 | bwd 512])
__device__ float g_gx[2 * 512 * 2048];      // [dir][t*16+b][4H]  (includes b_ih+b_hh)
__device__ float g_hde[512 * 512];          // hidden_de (t*16+b, h)
__device__ float g_hemA[512 * 512];         // h_em (t*16+b, e)
__device__ float g_col[4096 * 4608];        // im2col (b*256+hw, c*9+kh*3+kw)
__device__ float g_xt[4096 * 512];          // x_em as (b*256+hw, e)

// ---------------- f32x2 helpers ----------------
__device__ __forceinline__ void fma2(unsigned long long& d, unsigned long long a,
                                     unsigned long long b) {
    asm("fma.rn.f32x2 %0, %1, %2, %0;" : "+l"(d) : "l"(a), "l"(b));
}
__device__ __forceinline__ unsigned long long pk(float lo, float hi) {
    unsigned long long r;
    asm("mov.b64 %0, {%1, %2};" : "=l"(r) : "f"(lo), "f"(hi));
    return r;
}
__device__ __forceinline__ float2 upk(unsigned long long v) {
    float2 f;
    asm("mov.b64 {%0, %1}, %2;" : "=f"(f.x), "=f"(f.y) : "l"(v));
    return f;
}
__device__ __forceinline__ float tanh_fast(float x) {
    float y;
    asm("tanh.approx.f32 %0, %1;" : "=f"(y) : "f"(x));
    return y;
}

// ---------------- init ----------------
__global__ void k_zero() {
    int i = blockIdx.x * 256 + threadIdx.x;   // 16384 threads
    g_hT[0][i] = 0.f;
    g_cT[i] = 0.f;
}

// ---------------- im2col ----------------
__global__ void k_im2col(const float* __restrict__ cf) {
    int idx = blockIdx.x * 256 + threadIdx.x;         // < 4096*4608
    int kidx = idx % 4608;
    int m = idx / 4608;
    int kw = kidx % 3;
    int kh = (kidx / 3) % 3;
    int c = kidx / 9;
    int w = m & 31;
    int h = (m >> 5) & 7;
    int b = m >> 8;
    int ih = h + kh - 1, iw = w + kw - 1;
    float v = 0.f;
    if (ih >= 0 && ih < 8 && iw >= 0 && iw < 32)
        v = cf[((b * 512 + c) * 8 + ih) * 32 + iw];
    g_col[idx] = v;
}

// ---------------- 128x128 NT GEMM, f32x2, double-buffered smem ----------------
// C[m][n] = sum_k A[m][k] * W[n][k] + bias[n] (+ bias2[n])
__global__ __launch_bounds__(256) void k_gemm(
    const float* __restrict__ A, const float* __restrict__ W,
    const float* __restrict__ bias, const float* __restrict__ bias2,
    float* __restrict__ C, int M, int N, int K)
{
    __shared__ float As[2][16][128];
    __shared__ float Wd[2][16][256];   // duplicated: Wd[.][k][2n]=Wd[.][k][2n+1]=W[n][k]
    int tid = threadIdx.x;
    int bm = blockIdx.y << 7, bn = blockIdx.x << 7;
    int lr = tid >> 2;              // 0..63
    int lc = (tid & 3) << 2;        // 0,4,8,12
    const float* Ap  = A + (size_t)(bm + lr) * K + lc;
    const float* Ap2 = Ap + (size_t)64 * K;
    const float* Wp  = W + (size_t)(bn + lr) * K + lc;
    const float* Wp2 = Wp + (size_t)64 * K;
    int tx = tid & 15, ty = tid >> 4;
    int l2 = lr << 1;
    unsigned long long acc[4][8];
#pragma unroll
    for (int i = 0; i < 4; i++)
#pragma unroll
        for (int j = 0; j < 8; j++) acc[i][j] = 0ull;

    // prologue: load tile 0 into buffer 0
    {
        float4 a0 = *(const float4*)(Ap);
        float4 a1 = *(const float4*)(Ap2);
        float4 w0 = *(const float4*)(Wp);
        float4 w1 = *(const float4*)(Wp2);
        As[0][lc + 0][lr] = a0.x; As[0][lc + 1][lr] = a0.y;
        As[0][lc + 2][lr] = a0.z; As[0][lc + 3][lr] = a0.w;
        As[0][lc + 0][lr + 64] = a1.x; As[0][lc + 1][lr + 64] = a1.y;
        As[0][lc + 2][lr + 64] = a1.z; As[0][lc + 3][lr + 64] = a1.w;
        Wd[0][lc + 0][l2] = w0.x; Wd[0][lc + 0][l2 + 1] = w0.x;
        Wd[0][lc + 1][l2] = w0.y; Wd[0][lc + 1][l2 + 1] = w0.y;
        Wd[0][lc + 2][l2] = w0.z; Wd[0][lc + 2][l2 + 1] = w0.z;
        Wd[0][lc + 3][l2] = w0.w; Wd[0][lc + 3][l2 + 1] = w0.w;
        Wd[0][lc + 0][l2 + 128] = w1.x; Wd[0][lc + 0][l2 + 129] = w1.x;
        Wd[0][lc + 1][l2 + 128] = w1.y; Wd[0][lc + 1][l2 + 129] = w1.y;
        Wd[0][lc + 2][l2 + 128] = w1.z; Wd[0][lc + 2][l2 + 129] = w1.z;
        Wd[0][lc + 3][l2 + 128] = w1.w; Wd[0][lc + 3][l2 + 129] = w1.w;
    }
    __syncthreads();

    int nit = K >> 4;
    for (int it = 0; it < nit; it++) {
        // prefetch next tile (clamped on last iteration; redundant but in-bounds)
        int kn = ((it + 1 < nit) ? (it + 1) : it) << 4;
        float4 na0 = *(const float4*)(Ap + kn);
        float4 na1 = *(const float4*)(Ap2 + kn);
        float4 nw0 = *(const float4*)(Wp + kn);
        float4 nw1 = *(const float4*)(Wp2 + kn);
        int cur = it & 1, nxt = cur ^ 1;
#pragma unroll
        for (int kk = 0; kk < 16; kk++) {
            const ulonglong2* pa = (const ulonglong2*)&As[cur][kk][ty << 3];
            ulonglong2 ra0 = pa[0], ra1 = pa[1];
            const ulonglong2* pb = (const ulonglong2*)&Wd[cur][kk][tx << 4];
            ulonglong2 b0 = pb[0], b1 = pb[1], b2 = pb[2], b3 = pb[3];
            fma2(acc[0][0], ra0.x, b0.x); fma2(acc[0][1], ra0.x, b0.y);
            fma2(acc[0][2], ra0.x, b1.x); fma2(acc[0][3], ra0.x, b1.y);
            fma2(acc[0][4], ra0.x, b2.x); fma2(acc[0][5], ra0.x, b2.y);
            fma2(acc[0][6], ra0.x, b3.x); fma2(acc[0][7], ra0.x, b3.y);
            fma2(acc[1][0], ra0.y, b0.x); fma2(acc[1][1], ra0.y, b0.y);
            fma2(acc[1][2], ra0.y, b1.x); fma2(acc[1][3], ra0.y, b1.y);
            fma2(acc[1][4], ra0.y, b2.x); fma2(acc[1][5], ra0.y, b2.y);
            fma2(acc[1][6], ra0.y, b3.x); fma2(acc[1][7], ra0.y, b3.y);
            fma2(acc[2][0], ra1.x, b0.x); fma2(acc[2][1], ra1.x, b0.y);
            fma2(acc[2][2], ra1.x, b1.x); fma2(acc[2][3], ra1.x, b1.y);
            fma2(acc[2][4], ra1.x, b2.x); fma2(acc[2][5], ra1.x, b2.y);
            fma2(acc[2][6], ra1.x, b3.x); fma2(acc[2][7], ra1.x, b3.y);
            fma2(acc[3][0], ra1.y, b0.x); fma2(acc[3][1], ra1.y, b0.y);
            fma2(acc[3][2], ra1.y, b1.x); fma2(acc[3][3], ra1.y, b1.y);
            fma2(acc[3][4], ra1.y, b2.x); fma2(acc[3][5], ra1.y, b2.y);
            fma2(acc[3][6], ra1.y, b3.x); fma2(acc[3][7], ra1.y, b3.y);
        }
        // store prefetched tile into the other buffer (not read this iteration)
        As[nxt][lc + 0][lr] = na0.x; As[nxt][lc + 1][lr] = na0.y;
        As[nxt][lc + 2][lr] = na0.z; As[nxt][lc + 3][lr] = na0.w;
        As[nxt][lc + 0][lr + 64] = na1.x; As[nxt][lc + 1][lr + 64] = na1.y;
        As[nxt][lc + 2][lr + 64] = na1.z; As[nxt][lc + 3][lr + 64] = na1.w;
        Wd[nxt][lc + 0][l2] = nw0.x; Wd[nxt][lc + 0][l2 + 1] = nw0.x;
        Wd[nxt][lc + 1][l2] = nw0.y; Wd[nxt][lc + 1][l2 + 1] = nw0.y;
        Wd[nxt][lc + 2][l2] = nw0.z; Wd[nxt][lc + 2][l2 + 1] = nw0.z;
        Wd[nxt][lc + 3][l2] = nw0.w; Wd[nxt][lc + 3][l2 + 1] = nw0.w;
        Wd[nxt][lc + 0][l2 + 128] = nw1.x; Wd[nxt][lc + 0][l2 + 129] = nw1.x;
        Wd[nxt][lc + 1][l2 + 128] = nw1.y; Wd[nxt][lc + 1][l2 + 129] = nw1.y;
        Wd[nxt][lc + 2][l2 + 128] = nw1.z; Wd[nxt][lc + 2][l2 + 129] = nw1.z;
        Wd[nxt][lc + 3][l2 + 128] = nw1.w; Wd[nxt][lc + 3][l2 + 129] = nw1.w;
        __syncthreads();
    }
#pragma unroll
    for (int mp = 0; mp < 4; mp++) {
        int m0 = bm + (ty << 3) + (mp << 1);
#pragma unroll
        for (int j = 0; j < 8; j++) {
            int n = bn + (tx << 3) + j;
            float bv = bias[n] + (bias2 ? bias2[n] : 0.f);
            float2 v = upk(acc[mp][j]);
            C[(size_t)m0 * N + n] = v.x + bv;
            C[(size_t)(m0 + 1) * N + n] = v.y + bv;
        }
    }
}

// ---------------- 64x64 NT GEMM, f32x2 (small mats) ----------------
// Optional Cout: scatter C[m=t*16+b][n] -> Cout[(b*32+t)*1024 + n] (dec epilogue)
__global__ __launch_bounds__(256) void k_gemm64(
    const float* __restrict__ A, const float* __restrict__ W,
    const float* __restrict__ bias, const float* __restrict__ bias2,
    float* __restrict__ C, float* __restrict__ Cout, int M, int N, int K)
{
    __shared__ float As[16][64];
    __shared__ float Wd[16][128];
    int tid = threadIdx.x;
    int bm = blockIdx.y << 6, bn = blockIdx.x << 6;
    int lr = tid >> 2;
    int lc = (tid & 3) << 2;
    const float* Ap = A + (size_t)(bm + lr) * K + lc;
    const float* Wp = W + (size_t)(bn + lr) * K + lc;
    int tx = tid & 15, ty = tid >> 4;
    unsigned long long acc[2][4];
#pragma unroll
    for (int i = 0; i < 2; i++)
#pragma unroll
        for (int j = 0; j < 4; j++) acc[i][j] = 0ull;

    for (int k0 = 0; k0 < K; k0 += 16) {
        float4 a0 = *(const float4*)(Ap + k0);
        float4 w0 = *(const float4*)(Wp + k0);
        __syncthreads();
        As[lc + 0][lr] = a0.x; As[lc + 1][lr] = a0.y;
        As[lc + 2][lr] = a0.z; As[lc + 3][lr] = a0.w;
        int l2 = lr << 1;
        Wd[lc + 0][l2] = w0.x; Wd[lc + 0][l2 + 1] = w0.x;
        Wd[lc + 1][l2] = w0.y; Wd[lc + 1][l2 + 1] = w0.y;
        Wd[lc + 2][l2] = w0.z; Wd[lc + 2][l2 + 1] = w0.z;
        Wd[lc + 3][l2] = w0.w; Wd[lc + 3][l2 + 1] = w0.w;
        __syncthreads();
#pragma unroll
        for (int kk = 0; kk < 16; kk++) {
            ulonglong2 ra = *(const ulonglong2*)&As[kk][ty << 2];
            const ulonglong2* pb = (const ulonglong2*)&Wd[kk][tx << 3];
            ulonglong2 b0 = pb[0], b1 = pb[1];
            fma2(acc[0][0], ra.x, b0.x); fma2(acc[0][1], ra.x, b0.y);
            fma2(acc[0][2], ra.x, b1.x); fma2(acc[0][3], ra.x, b1.y);
            fma2(acc[1][0], ra.y, b0.x); fma2(acc[1][1], ra.y, b0.y);
            fma2(acc[1][2], ra.y, b1.x); fma2(acc[1][3], ra.y, b1.y);
        }
    }
#pragma unroll
    for (int mp = 0; mp < 2; mp++) {
        int m0 = bm + (ty << 2) + (mp << 1);
#pragma unroll
        for (int j = 0; j < 4; j++) {
            int n = bn + (tx << 2) + j;
            float bv = bias[n] + (bias2 ? bias2[n] : 0.f);
            float2 v = upk(acc[mp][j]);
            float o0 = v.x + bv, o1 = v.y + bv;
            C[(size_t)m0 * N + n] = o0;
            C[(size_t)(m0 + 1) * N + n] = o1;
            if (Cout) {
                int t0 = m0 >> 4, b0_ = m0 & 15;
                Cout[((b0_ << 5) + t0) * 1024 + n] = o0;
                int m1 = m0 + 1;
                int t1 = m1 >> 4, b1_ = m1 & 15;
                Cout[((b1_ << 5) + t1) * 1024 + n] = o1;
            }
        }
    }
}

// ---------------- LSTM step (double-buffered h: read s&1, write (s+1)&1) ----
__global__ __launch_bounds__(256) void k_lstm_step(
    const float* __restrict__ Whh_f, const float* __restrict__ Whh_b, int s)
{
    __shared__ float sbuf[8192];   // 32KB: phase1 hs[k][b], phase2 partials
    int dir = blockIdx.x & 1;
    int h0 = (blockIdx.x >> 1) << 5;
    int t = dir ? (31 - s) : s;
    const float* __restrict__ Whh = dir ? Whh_b : Whh_f;
    int tid = threadIdx.x;
    {
        const float4* hp4 = (const float4*)(g_hT[s & 1] + dir * 8192);
        float4* sb4 = (float4*)sbuf;
#pragma unroll
        for (int i = 0; i < 8; i++) sb4[tid + i * 256] = hp4[tid + i * 256];
    }
    __syncthreads();
    int kq = tid >> 6;
    int sub = tid & 63;
    int gate = sub >> 4;
    int hg = sub & 15;
    int h = h0 + (hg << 1);
    const float* wr0 = Whh + (size_t)(gate * 512 + h) * 512 + (kq << 7);
    const float* wr1 = wr0 + 512;
    unsigned long long acc[2][8];
#pragma unroll
    for (int p = 0; p < 2; p++)
#pragma unroll
        for (int j = 0; j < 8; j++) acc[p][j] = 0ull;

    for (int k4 = 0; k4 < 128; k4 += 4) {
        float4 wa = *(const float4*)(wr0 + k4);
        float4 wb = *(const float4*)(wr1 + k4);
        float wav[4] = {wa.x, wa.y, wa.z, wa.w};
        float wbv[4] = {wb.x, wb.y, wb.z, wb.w};
#pragma unroll
        for (int j = 0; j < 4; j++) {
            int k = (kq << 7) + k4 + j;
            unsigned long long w2a = pk(wav[j], wav[j]);
            unsigned long long w2b = pk(wbv[j], wbv[j]);
            const ulonglong2* hb = (const ulonglong2*)&sbuf[k << 4];
            ulonglong2 q0 = hb[0], q1 = hb[1], q2 = hb[2], q3 = hb[3];
            fma2(acc[0][0], w2a, q0.x); fma2(acc[0][1], w2a, q0.y);
            fma2(acc[0][2], w2a, q1.x); fma2(acc[0][3], w2a, q1.y);
            fma2(acc[0][4], w2a, q2.x); fma2(acc[0][5], w2a, q2.y);
            fma2(acc[0][6], w2a, q3.x); fma2(acc[0][7], w2a, q3.y);
            fma2(acc[1][0], w2b, q0.x); fma2(acc[1][1], w2b, q0.y);
            fma2(acc[1][2], w2b, q1.x); fma2(acc[1][3], w2b, q1.y);
            fma2(acc[1][4], w2b, q2.x); fma2(acc[1][5], w2b, q2.y);
            fma2(acc[1][6], w2b, q3.x); fma2(acc[1][7], w2b, q3.y);
        }
    }
    __syncthreads();   // done reading hs; reuse sbuf for partials
#pragma unroll
    for (int p = 0; p < 2; p++)
#pragma unroll
        for (int j = 0; j < 8; j++) {
            float2 v = upk(acc[p][j]);
            int base = ((((kq << 2) + gate) * 16 + hg) * 2 + p) * 16 + (j << 1);
            sbuf[base] = v.x;
            sbuf[base + 1] = v.y;
        }
    __syncthreads();
    const float* gx = g_gx + ((size_t)dir * 512 + t * 16) * 2048;
    float* hNext = g_hT[(s + 1) & 1];
    for (int it = tid; it < 512; it += 256) {
        int hloc = it >> 4, b = it & 15;
        int hgl = hloc >> 1, p = hloc & 1;
        float v[4];
#pragma unroll
        for (int g = 0; g < 4; g++) {
            int bi = ((g * 16 + hgl) * 2 + p) * 16 + b;
            v[g] = sbuf[bi] + sbuf[bi + 2048] + sbuf[bi + 4096] + sbuf[bi + 6144]
                 + gx[(size_t)b * 2048 + g * 512 + h0 + hloc];
        }
        float i_ = 1.f / (1.f + expf(-v[0]));
        float f_ = 1.f / (1.f + expf(-v[1]));
        float gg = tanhf(v[2]);
        float o_ = 1.f / (1.f + expf(-v[3]));
        int hh = h0 + hloc;
        int ci = dir * 8192 + hh * 16 + b;
        float c = f_ * g_cT[ci] + i_ * gg;
        g_cT[ci] = c;
        float hn = o_ * tanhf(c);
        hNext[ci] = hn;
        g_hseq[(t * 16 + b) * 1024 + dir * 512 + hh] = hn;
    }
}

// ---------------- fused attention (one CTA per (t,b)) ----------------
__global__ __launch_bounds__(256) void k_att(
    const float* __restrict__ w_att, const float* __restrict__ b_att,
    float* __restrict__ out)
{
    __shared__ float hv[512], wv[512], sc[256], red[256];
    int b = blockIdx.x & 15, t = blockIdx.x >> 4;
    int tid = threadIdx.x;
    hv[tid] = g_hemA[(t * 16 + b) * 512 + tid];
    hv[tid + 256] = g_hemA[(t * 16 + b) * 512 + tid + 256];
    wv[tid] = w_att[tid];
    wv[tid + 256] = w_att[tid + 256];
    __syncthreads();
    int lane = tid & 31, wrp = tid >> 5;
    const float* xb = g_xt + (size_t)b * 256 * 512;
    float batt = b_att[0];
    for (int hw = wrp; hw < 256; hw += 8) {
        const float* xr = xb + hw * 512;
        float sum = 0.f;
        for (int e = lane; e < 512; e += 32)
            sum += wv[e] * tanh_fast(xr[e] + hv[e]);
#pragma unroll
        for (int o = 16; o; o >>= 1) sum += __shfl_xor_sync(0xffffffffu, sum, o);
        if (lane == 0) sc[hw] = sum + batt;
    }
    __syncthreads();
    float s = sc[tid];
    red[tid] = s;
    __syncthreads();
    for (int st = 128; st; st >>= 1) {
        if (tid < st) red[tid] = fmaxf(red[tid], red[tid + st]);
        __syncthreads();
    }
    float mx = red[0];
    __syncthreads();
    float e = expf(s - mx);
    red[tid] = e;
    __syncthreads();
    for (int st = 128; st; st >>= 1) {
        if (tid < st) red[tid] += red[tid + st];
        __syncthreads();
    }
    float inv = 1.f / red[0];
    sc[tid] = e * inv;
    __syncthreads();
    float a0 = 0.f, a1 = 0.f;
    int e0 = tid, e1 = tid + 256;
    for (int hw = 0; hw < 256; hw++) {
        float al = sc[hw];
        const float* xr = xb + hw * 512;
        a0 += al * xr[e0];
        a1 += al * xr[e1];
    }
    float* orow = out + (size_t)((b << 5) + t) * 1024 + 512;
    orow[e0] = a0;
    orow[e1] = a1;
}

// ---------------- launch ----------------
extern "C" void kernel_launch(void* const* d_in, const int* in_sizes, int n_in,
                              void* d_out, int out_size) {
    const float* hidden_en = (const float*)d_in[0];
    const float* conv_f    = (const float*)d_in[1];
    const float* W_ih_f    = (const float*)d_in[2];
    const float* W_hh_f    = (const float*)d_in[3];
    const float* b_ih_f    = (const float*)d_in[4];
    const float* b_hh_f    = (const float*)d_in[5];
    const float* W_ih_b    = (const float*)d_in[6];
    const float* W_hh_b    = (const float*)d_in[7];
    const float* b_ih_b    = (const float*)d_in[8];
    const float* b_hh_b    = (const float*)d_in[9];
    const float* W_dec     = (const float*)d_in[10];
    const float* b_dec     = (const float*)d_in[11];
    const float* W_em      = (const float*)d_in[12];
    const float* b_em      = (const float*)d_in[13];
    const float* W_hem     = (const float*)d_in[14];
    const float* b_hem     = (const float*)d_in[15];
    const float* w_att     = (const float*)d_in[16];
    const float* b_att     = (const float*)d_in[17];
    float* out = (float*)d_out;

    float *p_gx, *p_col, *p_xt, *p_hseq, *p_hde, *p_hem;
    cudaGetSymbolAddress((void**)&p_gx, g_gx);
    cudaGetSymbolAddress((void**)&p_col, g_col);
    cudaGetSymbolAddress((void**)&p_xt, g_xt);
    cudaGetSymbolAddress((void**)&p_hseq, g_hseq);
    cudaGetSymbolAddress((void**)&p_hde, g_hde);
    cudaGetSymbolAddress((void**)&p_hem, g_hemA);

    k_zero<<<64, 256>>>();

    // conv path (independent of LSTM): im2col + big GEMM -> g_xt (B,HW,E)
    k_im2col<<<(4096 * 4608) / 256, 256>>>(conv_f);
    k_gemm<<<dim3(512 / 128, 4096 / 128), 256>>>(p_col, W_em, b_em, nullptr,
                                                 p_xt, 4096, 512, 4608);

    // input projections (bias = b_ih + b_hh folded in)
    k_gemm64<<<dim3(2048 / 64, 512 / 64), 256>>>(hidden_en, W_ih_f, b_ih_f, b_hh_f,
                                                 p_gx, nullptr, 512, 2048, 512);
    k_gemm64<<<dim3(2048 / 64, 512 / 64), 256>>>(hidden_en, W_ih_b, b_ih_b, b_hh_b,
                                                 p_gx + 512 * 2048, nullptr, 512, 2048, 512);

    // bidirectional LSTM recurrence
    for (int s = 0; s < 32; s++)
        k_lstm_step<<<32, 256>>>(W_hh_f, W_hh_b, s);

    // linear_decode: writes g_hde and scatters hidden_de into out[:, :, 0:512]
    k_gemm64<<<dim3(512 / 64, 512 / 64), 256>>>(p_hseq, W_dec, b_dec, nullptr,
                                                p_hde, out, 512, 512, 1024);
    // h_em projection
    k_gemm64<<<dim3(512 / 64, 512 / 64), 256>>>(p_hde, W_hem, b_hem, nullptr,
                                                p_hem, nullptr, 512, 512, 512);
    // attention -> out[:, :, 512:1024]
    k_att<<<512, 256>>>(w_att, b_att, out);
}

// round 5
// speedup vs baseline: 1.0017x; 1.0017x over previous
#include <cuda_runtime.h>
#include <math.h>
#include <stdint.h>

// ---------------- problem dims ----------------
// T=32 B=16 D=512 H=512 E=512 C=512 FH=8 FW=32, HW=256
// out: (B, T, H+E) = (16, 32, 1024) float32

// ---------------- device scratch ----------------
__device__ float g_hT[2][2 * 512 * 16];     // h state, double-buffered: [phase][dir*8192 + h*16 + b]
__device__ float g_cT[2 * 512 * 16];        // c state [dir][h][b]
__device__ float g_hseq[512 * 1024];        // (t*16+b, [fwd 512 | bwd 512])
__device__ float g_gx[2 * 512 * 2048];      // [dir][t*16+b][4H]  (includes b_ih+b_hh)
__device__ float g_hde[512 * 512];          // hidden_de (t*16+b, h)
__device__ float g_hemA[512 * 512];         // h_em (t*16+b, e)
__device__ float g_col[4096 * 4608];        // im2col (b*256+hw, c*9+kh*3+kw)
__device__ float g_xt[4096 * 512];          // x_em as (b*256+hw, e)

// ---------------- f32x2 helpers ----------------
__device__ __forceinline__ void fma2(unsigned long long& d, unsigned long long a,
                                     unsigned long long b) {
    asm("fma.rn.f32x2 %0, %1, %2, %0;" : "+l"(d) : "l"(a), "l"(b));
}
__device__ __forceinline__ unsigned long long pk(float lo, float hi) {
    unsigned long long r;
    asm("mov.b64 %0, {%1, %2};" : "=l"(r) : "f"(lo), "f"(hi));
    return r;
}
__device__ __forceinline__ float2 upk(unsigned long long v) {
    float2 f;
    asm("mov.b64 {%0, %1}, %2;" : "=f"(f.x), "=f"(f.y) : "l"(v));
    return f;
}
__device__ __forceinline__ float tanh_fast(float x) {
    float y;
    asm("tanh.approx.f32 %0, %1;" : "=f"(y) : "f"(x));
    return y;
}

// ---------------- init ----------------
__global__ void k_zero() {
    int i = blockIdx.x * 256 + threadIdx.x;   // 16384 threads
    g_hT[0][i] = 0.f;
    g_cT[i] = 0.f;
}

// ---------------- im2col ----------------
__global__ void k_im2col(const float* __restrict__ cf) {
    int idx = blockIdx.x * 256 + threadIdx.x;         // < 4096*4608
    int kidx = idx % 4608;
    int m = idx / 4608;
    int kw = kidx % 3;
    int kh = (kidx / 3) % 3;
    int c = kidx / 9;
    int w = m & 31;
    int h = (m >> 5) & 7;
    int b = m >> 8;
    int ih = h + kh - 1, iw = w + kw - 1;
    float v = 0.f;
    if (ih >= 0 && ih < 8 && iw >= 0 && iw < 32)
        v = cf[((b * 512 + c) * 8 + ih) * 32 + iw];
    g_col[idx] = v;
}

// ---------------- 128x128 NT GEMM, f32x2, double-buffered smem ----------------
// C[m][n] = sum_k A[m][k] * W[n][k] + bias[n] (+ bias2[n])
__global__ __launch_bounds__(256) void k_gemm(
    const float* __restrict__ A, const float* __restrict__ W,
    const float* __restrict__ bias, const float* __restrict__ bias2,
    float* __restrict__ C, int M, int N, int K)
{
    __shared__ float As[2][16][128];
    __shared__ float Wd[2][16][256];   // duplicated: Wd[.][k][2n]=Wd[.][k][2n+1]=W[n][k]
    int tid = threadIdx.x;
    int bm = blockIdx.y << 7, bn = blockIdx.x << 7;
    int lr = tid >> 2;              // 0..63
    int lc = (tid & 3) << 2;        // 0,4,8,12
    const float* Ap  = A + (size_t)(bm + lr) * K + lc;
    const float* Ap2 = Ap + (size_t)64 * K;
    const float* Wp  = W + (size_t)(bn + lr) * K + lc;
    const float* Wp2 = Wp + (size_t)64 * K;
    int tx = tid & 15, ty = tid >> 4;
    int l2 = lr << 1;
    unsigned long long acc[4][8];
#pragma unroll
    for (int i = 0; i < 4; i++)
#pragma unroll
        for (int j = 0; j < 8; j++) acc[i][j] = 0ull;

    // prologue: load tile 0 into buffer 0
    {
        float4 a0 = *(const float4*)(Ap);
        float4 a1 = *(const float4*)(Ap2);
        float4 w0 = *(const float4*)(Wp);
        float4 w1 = *(const float4*)(Wp2);
        As[0][lc + 0][lr] = a0.x; As[0][lc + 1][lr] = a0.y;
        As[0][lc + 2][lr] = a0.z; As[0][lc + 3][lr] = a0.w;
        As[0][lc + 0][lr + 64] = a1.x; As[0][lc + 1][lr + 64] = a1.y;
        As[0][lc + 2][lr + 64] = a1.z; As[0][lc + 3][lr + 64] = a1.w;
        Wd[0][lc + 0][l2] = w0.x; Wd[0][lc + 0][l2 + 1] = w0.x;
        Wd[0][lc + 1][l2] = w0.y; Wd[0][lc + 1][l2 + 1] = w0.y;
        Wd[0][lc + 2][l2] = w0.z; Wd[0][lc + 2][l2 + 1] = w0.z;
        Wd[0][lc + 3][l2] = w0.w; Wd[0][lc + 3][l2 + 1] = w0.w;
        Wd[0][lc + 0][l2 + 128] = w1.x; Wd[0][lc + 0][l2 + 129] = w1.x;
        Wd[0][lc + 1][l2 + 128] = w1.y; Wd[0][lc + 1][l2 + 129] = w1.y;
        Wd[0][lc + 2][l2 + 128] = w1.z; Wd[0][lc + 2][l2 + 129] = w1.z;
        Wd[0][lc + 3][l2 + 128] = w1.w; Wd[0][lc + 3][l2 + 129] = w1.w;
    }
    __syncthreads();

    int nit = K >> 4;
    for (int it = 0; it < nit; it++) {
        // prefetch next tile (clamped on last iteration; redundant but in-bounds)
        int kn = ((it + 1 < nit) ? (it + 1) : it) << 4;
        float4 na0 = *(const float4*)(Ap + kn);
        float4 na1 = *(const float4*)(Ap2 + kn);
        float4 nw0 = *(const float4*)(Wp + kn);
        float4 nw1 = *(const float4*)(Wp2 + kn);
        int cur = it & 1, nxt = cur ^ 1;
#pragma unroll
        for (int kk = 0; kk < 16; kk++) {
            const ulonglong2* pa = (const ulonglong2*)&As[cur][kk][ty << 3];
            ulonglong2 ra0 = pa[0], ra1 = pa[1];
            const ulonglong2* pb = (const ulonglong2*)&Wd[cur][kk][tx << 4];
            ulonglong2 b0 = pb[0], b1 = pb[1], b2 = pb[2], b3 = pb[3];
            fma2(acc[0][0], ra0.x, b0.x); fma2(acc[0][1], ra0.x, b0.y);
            fma2(acc[0][2], ra0.x, b1.x); fma2(acc[0][3], ra0.x, b1.y);
            fma2(acc[0][4], ra0.x, b2.x); fma2(acc[0][5], ra0.x, b2.y);
            fma2(acc[0][6], ra0.x, b3.x); fma2(acc[0][7], ra0.x, b3.y);
            fma2(acc[1][0], ra0.y, b0.x); fma2(acc[1][1], ra0.y, b0.y);
            fma2(acc[1][2], ra0.y, b1.x); fma2(acc[1][3], ra0.y, b1.y);
            fma2(acc[1][4], ra0.y, b2.x); fma2(acc[1][5], ra0.y, b2.y);
            fma2(acc[1][6], ra0.y, b3.x); fma2(acc[1][7], ra0.y, b3.y);
            fma2(acc[2][0], ra1.x, b0.x); fma2(acc[2][1], ra1.x, b0.y);
            fma2(acc[2][2], ra1.x, b1.x); fma2(acc[2][3], ra1.x, b1.y);
            fma2(acc[2][4], ra1.x, b2.x); fma2(acc[2][5], ra1.x, b2.y);
            fma2(acc[2][6], ra1.x, b3.x); fma2(acc[2][7], ra1.x, b3.y);
            fma2(acc[3][0], ra1.y, b0.x); fma2(acc[3][1], ra1.y, b0.y);
            fma2(acc[3][2], ra1.y, b1.x); fma2(acc[3][3], ra1.y, b1.y);
            fma2(acc[3][4], ra1.y, b2.x); fma2(acc[3][5], ra1.y, b2.y);
            fma2(acc[3][6], ra1.y, b3.x); fma2(acc[3][7], ra1.y, b3.y);
        }
        // store prefetched tile into the other buffer (not read this iteration)
        As[nxt][lc + 0][lr] = na0.x; As[nxt][lc + 1][lr] = na0.y;
        As[nxt][lc + 2][lr] = na0.z; As[nxt][lc + 3][lr] = na0.w;
        As[nxt][lc + 0][lr + 64] = na1.x; As[nxt][lc + 1][lr + 64] = na1.y;
        As[nxt][lc + 2][lr + 64] = na1.z; As[nxt][lc + 3][lr + 64] = na1.w;
        Wd[nxt][lc + 0][l2] = nw0.x; Wd[nxt][lc + 0][l2 + 1] = nw0.x;
        Wd[nxt][lc + 1][l2] = nw0.y; Wd[nxt][lc + 1][l2 + 1] = nw0.y;
        Wd[nxt][lc + 2][l2] = nw0.z; Wd[nxt][lc + 2][l2 + 1] = nw0.z;
        Wd[nxt][lc + 3][l2] = nw0.w; Wd[nxt][lc + 3][l2 + 1] = nw0.w;
        Wd[nxt][lc + 0][l2 + 128] = nw1.x; Wd[nxt][lc + 0][l2 + 129] = nw1.x;
        Wd[nxt][lc + 1][l2 + 128] = nw1.y; Wd[nxt][lc + 1][l2 + 129] = nw1.y;
        Wd[nxt][lc + 2][l2 + 128] = nw1.z; Wd[nxt][lc + 2][l2 + 129] = nw1.z;
        Wd[nxt][lc + 3][l2 + 128] = nw1.w; Wd[nxt][lc + 3][l2 + 129] = nw1.w;
        __syncthreads();
    }
#pragma unroll
    for (int mp = 0; mp < 4; mp++) {
        int m0 = bm + (ty << 3) + (mp << 1);
#pragma unroll
        for (int j = 0; j < 8; j++) {
            int n = bn + (tx << 3) + j;
            float bv = bias[n] + (bias2 ? bias2[n] : 0.f);
            float2 v = upk(acc[mp][j]);
            C[(size_t)m0 * N + n] = v.x + bv;
            C[(size_t)(m0 + 1) * N + n] = v.y + bv;
        }
    }
}

// ---------------- 64x64 NT GEMM, f32x2 (small mats) ----------------
// Optional Cout: scatter C[m=t*16+b][n] -> Cout[(b*32+t)*1024 + n] (dec epilogue)
__global__ __launch_bounds__(256) void k_gemm64(
    const float* __restrict__ A, const float* __restrict__ W,
    const float* __restrict__ bias, const float* __restrict__ bias2,
    float* __restrict__ C, float* __restrict__ Cout, int M, int N, int K)
{
    __shared__ float As[16][64];
    __shared__ float Wd[16][128];
    int tid = threadIdx.x;
    int bm = blockIdx.y << 6, bn = blockIdx.x << 6;
    int lr = tid >> 2;
    int lc = (tid & 3) << 2;
    const float* Ap = A + (size_t)(bm + lr) * K + lc;
    const float* Wp = W + (size_t)(bn + lr) * K + lc;
    int tx = tid & 15, ty = tid >> 4;
    unsigned long long acc[2][4];
#pragma unroll
    for (int i = 0; i < 2; i++)
#pragma unroll
        for (int j = 0; j < 4; j++) acc[i][j] = 0ull;

    for (int k0 = 0; k0 < K; k0 += 16) {
        float4 a0 = *(const float4*)(Ap + k0);
        float4 w0 = *(const float4*)(Wp + k0);
        __syncthreads();
        As[lc + 0][lr] = a0.x; As[lc + 1][lr] = a0.y;
        As[lc + 2][lr] = a0.z; As[lc + 3][lr] = a0.w;
        int l2 = lr << 1;
        Wd[lc + 0][l2] = w0.x; Wd[lc + 0][l2 + 1] = w0.x;
        Wd[lc + 1][l2] = w0.y; Wd[lc + 1][l2 + 1] = w0.y;
        Wd[lc + 2][l2] = w0.z; Wd[lc + 2][l2 + 1] = w0.z;
        Wd[lc + 3][l2] = w0.w; Wd[lc + 3][l2 + 1] = w0.w;
        __syncthreads();
#pragma unroll
        for (int kk = 0; kk < 16; kk++) {
            ulonglong2 ra = *(const ulonglong2*)&As[kk][ty << 2];
            const ulonglong2* pb = (const ulonglong2*)&Wd[kk][tx << 3];
            ulonglong2 b0 = pb[0], b1 = pb[1];
            fma2(acc[0][0], ra.x, b0.x); fma2(acc[0][1], ra.x, b0.y);
            fma2(acc[0][2], ra.x, b1.x); fma2(acc[0][3], ra.x, b1.y);
            fma2(acc[1][0], ra.y, b0.x); fma2(acc[1][1], ra.y, b0.y);
            fma2(acc[1][2], ra.y, b1.x); fma2(acc[1][3], ra.y, b1.y);
        }
    }
#pragma unroll
    for (int mp = 0; mp < 2; mp++) {
        int m0 = bm + (ty << 2) + (mp << 1);
#pragma unroll
        for (int j = 0; j < 4; j++) {
            int n = bn + (tx << 2) + j;
            float bv = bias[n] + (bias2 ? bias2[n] : 0.f);
            float2 v = upk(acc[mp][j]);
            float o0 = v.x + bv, o1 = v.y + bv;
            C[(size_t)m0 * N + n] = o0;
            C[(size_t)(m0 + 1) * N + n] = o1;
            if (Cout) {
                int t0 = m0 >> 4, b0_ = m0 & 15;
                Cout[((b0_ << 5) + t0) * 1024 + n] = o0;
                int m1 = m0 + 1;
                int t1 = m1 >> 4, b1_ = m1 & 15;
                Cout[((b1_ << 5) + t1) * 1024 + n] = o1;
            }
        }
    }
}

// ---------------- LSTM step (double-buffered h: read s&1, write (s+1)&1) ----
__global__ __launch_bounds__(256) void k_lstm_step(
    const float* __restrict__ Whh_f, const float* __restrict__ Whh_b, int s)
{
    __shared__ float sbuf[8192];   // 32KB: phase1 hs[k][b], phase2 partials
    int dir = blockIdx.x & 1;
    int h0 = (blockIdx.x >> 1) << 5;
    int t = dir ? (31 - s) : s;
    const float* __restrict__ Whh = dir ? Whh_b : Whh_f;
    int tid = threadIdx.x;
    {
        const float4* hp4 = (const float4*)(g_hT[s & 1] + dir * 8192);
        float4* sb4 = (float4*)sbuf;
#pragma unroll
        for (int i = 0; i < 8; i++) sb4[tid + i * 256] = hp4[tid + i * 256];
    }
    __syncthreads();
    int kq = tid >> 6;
    int sub = tid & 63;
    int gate = sub >> 4;
    int hg = sub & 15;
    int h = h0 + (hg << 1);
    const float* wr0 = Whh + (size_t)(gate * 512 + h) * 512 + (kq << 7);
    const float* wr1 = wr0 + 512;
    unsigned long long acc[2][8];
#pragma unroll
    for (int p = 0; p < 2; p++)
#pragma unroll
        for (int j = 0; j < 8; j++) acc[p][j] = 0ull;

    for (int k4 = 0; k4 < 128; k4 += 4) {
        float4 wa = *(const float4*)(wr0 + k4);
        float4 wb = *(const float4*)(wr1 + k4);
        float wav[4] = {wa.x, wa.y, wa.z, wa.w};
        float wbv[4] = {wb.x, wb.y, wb.z, wb.w};
#pragma unroll
        for (int j = 0; j < 4; j++) {
            int k = (kq << 7) + k4 + j;
            unsigned long long w2a = pk(wav[j], wav[j]);
            unsigned long long w2b = pk(wbv[j], wbv[j]);
            const ulonglong2* hb = (const ulonglong2*)&sbuf[k << 4];
            ulonglong2 q0 = hb[0], q1 = hb[1], q2 = hb[2], q3 = hb[3];
            fma2(acc[0][0], w2a, q0.x); fma2(acc[0][1], w2a, q0.y);
            fma2(acc[0][2], w2a, q1.x); fma2(acc[0][3], w2a, q1.y);
            fma2(acc[0][4], w2a, q2.x); fma2(acc[0][5], w2a, q2.y);
            fma2(acc[0][6], w2a, q3.x); fma2(acc[0][7], w2a, q3.y);
            fma2(acc[1][0], w2b, q0.x); fma2(acc[1][1], w2b, q0.y);
            fma2(acc[1][2], w2b, q1.x); fma2(acc[1][3], w2b, q1.y);
            fma2(acc[1][4], w2b, q2.x); fma2(acc[1][5], w2b, q2.y);
            fma2(acc[1][6], w2b, q3.x); fma2(acc[1][7], w2b, q3.y);
        }
    }
    __syncthreads();   // done reading hs; reuse sbuf for partials
#pragma unroll
    for (int p = 0; p < 2; p++)
#pragma unroll
        for (int j = 0; j < 8; j++) {
            float2 v = upk(acc[p][j]);
            int base = ((((kq << 2) + gate) * 16 + hg) * 2 + p) * 16 + (j << 1);
            sbuf[base] = v.x;
            sbuf[base + 1] = v.y;
        }
    __syncthreads();
    const float* gx = g_gx + ((size_t)dir * 512 + t * 16) * 2048;
    float* hNext = g_hT[(s + 1) & 1];
    for (int it = tid; it < 512; it += 256) {
        int hloc = it >> 4, b = it & 15;
        int hgl = hloc >> 1, p = hloc & 1;
        float v[4];
#pragma unroll
        for (int g = 0; g < 4; g++) {
            int bi = ((g * 16 + hgl) * 2 + p) * 16 + b;
            v[g] = sbuf[bi] + sbuf[bi + 2048] + sbuf[bi + 4096] + sbuf[bi + 6144]
                 + gx[(size_t)b * 2048 + g * 512 + h0 + hloc];
        }
        float i_ = 1.f / (1.f + expf(-v[0]));
        float f_ = 1.f / (1.f + expf(-v[1]));
        float gg = tanhf(v[2]);
        float o_ = 1.f / (1.f + expf(-v[3]));
        int hh = h0 + hloc;
        int ci = dir * 8192 + hh * 16 + b;
        float c = f_ * g_cT[ci] + i_ * gg;
        g_cT[ci] = c;
        float hn = o_ * tanhf(c);
        hNext[ci] = hn;
        g_hseq[(t * 16 + b) * 1024 + dir * 512 + hh] = hn;
    }
}

// ---------------- fused attention (one CTA per (t,b)) ----------------
__global__ __launch_bounds__(256) void k_att(
    const float* __restrict__ w_att, const float* __restrict__ b_att,
    float* __restrict__ out)
{
    __shared__ float hv[512], wv[512], sc[256], red[256];
    int b = blockIdx.x & 15, t = blockIdx.x >> 4;
    int tid = threadIdx.x;
    hv[tid] = g_hemA[(t * 16 + b) * 512 + tid];
    hv[tid + 256] = g_hemA[(t * 16 + b) * 512 + tid + 256];
    wv[tid] = w_att[tid];
    wv[tid + 256] = w_att[tid + 256];
    __syncthreads();
    int lane = tid & 31, wrp = tid >> 5;
    const float* xb = g_xt + (size_t)b * 256 * 512;
    float batt = b_att[0];
    for (int hw = wrp; hw < 256; hw += 8) {
        const float* xr = xb + hw * 512;
        float sum = 0.f;
        for (int e = lane; e < 512; e += 32)
            sum += wv[e] * tanh_fast(xr[e] + hv[e]);
#pragma unroll
        for (int o = 16; o; o >>= 1) sum += __shfl_xor_sync(0xffffffffu, sum, o);
        if (lane == 0) sc[hw] = sum + batt;
    }
    __syncthreads();
    float s = sc[tid];
    red[tid] = s;
    __syncthreads();
    for (int st = 128; st; st >>= 1) {
        if (tid < st) red[tid] = fmaxf(red[tid], red[tid + st]);
        __syncthreads();
    }
    float mx = red[0];
    __syncthreads();
    float e = expf(s - mx);
    red[tid] = e;
    __syncthreads();
    for (int st = 128; st; st >>= 1) {
        if (tid < st) red[tid] += red[tid + st];
        __syncthreads();
    }
    float inv = 1.f / red[0];
    sc[tid] = e * inv;
    __syncthreads();
    float a0 = 0.f, a1 = 0.f;
    int e0 = tid, e1 = tid + 256;
    for (int hw = 0; hw < 256; hw++) {
        float al = sc[hw];
        const float* xr = xb + hw * 512;
        a0 += al * xr[e0];
        a1 += al * xr[e1];
    }
    float* orow = out + (size_t)((b << 5) + t) * 1024 + 512;
    orow[e0] = a0;
    orow[e1] = a1;
}

// ---------------- launch ----------------
extern "C" void kernel_launch(void* const* d_in, const int* in_sizes, int n_in,
                              void* d_out, int out_size) {
    const float* hidden_en = (const float*)d_in[0];
    const float* conv_f    = (const float*)d_in[1];
    const float* W_ih_f    = (const float*)d_in[2];
    const float* W_hh_f    = (const float*)d_in[3];
    const float* b_ih_f    = (const float*)d_in[4];
    const float* b_hh_f    = (const float*)d_in[5];
    const float* W_ih_b    = (const float*)d_in[6];
    const float* W_hh_b    = (const float*)d_in[7];
    const float* b_ih_b    = (const float*)d_in[8];
    const float* b_hh_b    = (const float*)d_in[9];
    const float* W_dec     = (const float*)d_in[10];
    const float* b_dec     = (const float*)d_in[11];
    const float* W_em      = (const float*)d_in[12];
    const float* b_em      = (const float*)d_in[13];
    const float* W_hem     = (const float*)d_in[14];
    const float* b_hem     = (const float*)d_in[15];
    const float* w_att     = (const float*)d_in[16];
    const float* b_att     = (const float*)d_in[17];
    float* out = (float*)d_out;

    float *p_gx, *p_col, *p_xt, *p_hseq, *p_hde, *p_hem;
    cudaGetSymbolAddress((void**)&p_gx, g_gx);
    cudaGetSymbolAddress((void**)&p_col, g_col);
    cudaGetSymbolAddress((void**)&p_xt, g_xt);
    cudaGetSymbolAddress((void**)&p_hseq, g_hseq);
    cudaGetSymbolAddress((void**)&p_hde, g_hde);
    cudaGetSymbolAddress((void**)&p_hem, g_hemA);

    k_zero<<<64, 256>>>();

    // conv path (independent of LSTM): im2col + big GEMM -> g_xt (B,HW,E)
    k_im2col<<<(4096 * 4608) / 256, 256>>>(conv_f);
    k_gemm<<<dim3(512 / 128, 4096 / 128), 256>>>(p_col, W_em, b_em, nullptr,
                                                 p_xt, 4096, 512, 4608);

    // input projections (bias = b_ih + b_hh folded in)
    k_gemm64<<<dim3(2048 / 64, 512 / 64), 256>>>(hidden_en, W_ih_f, b_ih_f, b_hh_f,
                                                 p_gx, nullptr, 512, 2048, 512);
    k_gemm64<<<dim3(2048 / 64, 512 / 64), 256>>>(hidden_en, W_ih_b, b_ih_b, b_hh_b,
                                                 p_gx + 512 * 2048, nullptr, 512, 2048, 512);

    // bidirectional LSTM recurrence
    for (int s = 0; s < 32; s++)
        k_lstm_step<<<32, 256>>>(W_hh_f, W_hh_b, s);

    // linear_decode: writes g_hde and scatters hidden_de into out[:, :, 0:512]
    k_gemm64<<<dim3(512 / 64, 512 / 64), 256>>>(p_hseq, W_dec, b_dec, nullptr,
                                                p_hde, out, 512, 512, 1024);
    // h_em projection
    k_gemm64<<<dim3(512 / 64, 512 / 64), 256>>>(p_hde, W_hem, b_hem, nullptr,
                                                p_hem, nullptr, 512, 512, 512);
    // attention -> out[:, :, 512:1024]
    k_att<<<512, 256>>>(w_att, b_att, out);
}

// round 7
// speedup vs baseline: 1.7703x; 1.7673x over previous
#include <cuda_runtime.h>
#include <cuda_bf16.h>
#include <math.h>
#include <stdint.h>

typedef __nv_bfloat16 bf16;

// ---------------- scratch ----------------
__device__ float g_hT[2][16384];
__device__ float g_cT[16384];
__device__ float g_hseq[512 * 1024];
__device__ float g_gx[2 * 512 * 2048];
__device__ float g_hemA[512 * 512];
__device__ float g_xt[4096 * 512];
__device__ bf16 g_col3[4096u * 13824u];
__device__ bf16 g_wem3[512 * 13824];
__device__ bf16 g_en3[512 * 1536];
__device__ bf16 g_wihf3[2048 * 1536], g_wihb3[2048 * 1536];
__device__ bf16 g_wdec3[512 * 3072];
__device__ bf16 g_whem3[512 * 1536];
__device__ bf16 g_hseq3[512 * 3072];
__device__ bf16 g_hde3[512 * 1536];

// ---------------- helpers ----------------
__device__ __forceinline__ void fma2(unsigned long long& d, unsigned long long a, unsigned long long b) {
    asm("fma.rn.f32x2 %0, %1, %2, %0;" : "+l"(d) : "l"(a), "l"(b));
}
__device__ __forceinline__ unsigned long long pk(float lo, float hi) {
    unsigned long long r;
    asm("mov.b64 %0, {%1, %2};" : "=l"(r) : "f"(lo), "f"(hi));
    return r;
}
__device__ __forceinline__ float2 upk(unsigned long long v) {
    float2 f;
    asm("mov.b64 {%0, %1}, %2;" : "=f"(f.x), "=f"(f.y) : "l"(v));
    return f;
}
__device__ __forceinline__ float tanh_fast(float x) {
    float y;
    asm("tanh.approx.f32 %0, %1;" : "=f"(y) : "f"(x));
    return y;
}

// ---------------- init & converts ----------------
__global__ void k_zero() {
    int i = blockIdx.x * 256 + threadIdx.x;
    g_hT[0][i] = 0.f;
    g_cT[i] = 0.f;
}
// A-side triple: [hi | hi | lo]
__global__ void k_cvtA3(const float* __restrict__ s, bf16* __restrict__ d, int K, int n) {
    int i = blockIdx.x * 256 + threadIdx.x;
    if (i >= n) return;
    int m = i / K, k = i % K;
    float v = s[i];
    bf16 h = __float2bfloat16(v);
    bf16 l = __float2bfloat16(v - __bfloat162float(h));
    size_t base = (size_t)m * 3 * K;
    d[base + k] = h; d[base + K + k] = h; d[base + 2 * K + k] = l;
}
// B-side triple: [hi | lo | hi]
__global__ void k_cvtB3(const float* __restrict__ s, bf16* __restrict__ d, int K, int n) {
    int i = blockIdx.x * 256 + threadIdx.x;
    if (i >= n) return;
    int m = i / K, k = i % K;
    float v = s[i];
    bf16 h = __float2bfloat16(v);
    bf16 l = __float2bfloat16(v - __bfloat162float(h));
    size_t base = (size_t)m * 3 * K;
    d[base + k] = h; d[base + K + k] = l; d[base + 2 * K + k] = h;
}
// im2col -> A-side triple layout, K=4608
__global__ void k_im2col3(const float* __restrict__ cf) {
    int idx = blockIdx.x * 256 + threadIdx.x;   // < 4096*4608
    int k = idx % 4608, m = idx / 4608;
    int kw = k % 3, kh = (k / 3) % 3, c = k / 9;
    int w = m & 31, h = (m >> 5) & 7, b = m >> 8;
    int ih = h + kh - 1, iw = w + kw - 1;
    float v = 0.f;
    if (ih >= 0 && ih < 8 && iw >= 0 && iw < 32) v = cf[((b * 512 + c) * 8 + ih) * 32 + iw];
    bf16 hv = __float2bfloat16(v);
    bf16 lv = __float2bfloat16(v - __bfloat162float(hv));
    size_t base = (size_t)m * 13824;
    g_col3[base + k] = hv; g_col3[base + 4608 + k] = hv; g_col3[base + 9216 + k] = lv;
}

// ---------------- HMMA bf16 NT GEMM (CTA 128x128, k-chunk 32) ----------------
#define PAD 56
__device__ __forceinline__ void ldtile(bf16* ds, const bf16* __restrict__ src,
                                       int row0, int K3, int k0, int tid) {
#pragma unroll
    for (int j = 0; j < 2; j++) {
        int ch = tid + (j << 8);          // 0..511
        int row = ch >> 2, c = ch & 3;
        uint4 v = *(const uint4*)(src + (size_t)(row0 + row) * K3 + k0 + (c << 3));
        *(uint4*)(ds + row * PAD + (c << 3)) = v;
    }
}

__global__ __launch_bounds__(256) void k_mma_gemm(
    const bf16* __restrict__ A3, const bf16* __restrict__ B3,
    const float* __restrict__ bias, const float* __restrict__ bias2,
    float* __restrict__ Cf, bf16* __restrict__ C3, int C3K,
    float* __restrict__ Cscat, int N, int K3)
{
    __shared__ bf16 As[128 * PAD], Bs[128 * PAD];
    int tid = threadIdx.x, lane = tid & 31, wid = tid >> 5;
    int g = lane >> 2, t2 = (lane & 3) << 1;
    int bm = blockIdx.y << 7, bn = blockIdx.x << 7;
    int wm = (wid >> 1) << 5, wn = (wid & 1) << 6;
    float acc[2][8][4];
#pragma unroll
    for (int mt = 0; mt < 2; mt++)
#pragma unroll
        for (int nt = 0; nt < 8; nt++)
#pragma unroll
            for (int q = 0; q < 4; q++) acc[mt][nt][q] = 0.f;

    for (int k0 = 0; k0 < K3; k0 += 32) {
        __syncthreads();
        ldtile(As, A3, bm, K3, k0, tid);
        ldtile(Bs, B3, bn, K3, k0, tid);
        __syncthreads();
#pragma unroll
        for (int kk = 0; kk < 2; kk++) {
            int kb = kk << 4;
            uint32_t a[2][4], b[8][2];
#pragma unroll
            for (int mt = 0; mt < 2; mt++) {
                const bf16* ab = &As[(wm + (mt << 4) + g) * PAD + kb + t2];
                a[mt][0] = *(const uint32_t*)ab;
                a[mt][1] = *(const uint32_t*)(ab + 8 * PAD);
                a[mt][2] = *(const uint32_t*)(ab + 8);
                a[mt][3] = *(const uint32_t*)(ab + 8 * PAD + 8);
            }
#pragma unroll
            for (int nt = 0; nt < 8; nt++) {
                const bf16* bb = &Bs[(wn + (nt << 3) + g) * PAD + kb + t2];
                b[nt][0] = *(const uint32_t*)bb;
                b[nt][1] = *(const uint32_t*)(bb + 8);
            }
#pragma unroll
            for (int mt = 0; mt < 2; mt++)
#pragma unroll
                for (int nt = 0; nt < 8; nt++)
                    asm volatile(
                        "mma.sync.aligned.m16n8k16.row.col.f32.bf16.bf16.f32 "
                        "{%0,%1,%2,%3},{%4,%5,%6,%7},{%8,%9},{%0,%1,%2,%3};"
                        : "+f"(acc[mt][nt][0]), "+f"(acc[mt][nt][1]),
                          "+f"(acc[mt][nt][2]), "+f"(acc[mt][nt][3])
                        : "r"(a[mt][0]), "r"(a[mt][1]), "r"(a[mt][2]), "r"(a[mt][3]),
                          "r"(b[nt][0]), "r"(b[nt][1]));
        }
    }
#pragma unroll
    for (int mt = 0; mt < 2; mt++)
#pragma unroll
        for (int nt = 0; nt < 8; nt++) {
            int r0 = bm + wm + (mt << 4) + g;
            int c0 = bn + wn + (nt << 3) + t2;
            float bv0 = bias[c0] + (bias2 ? bias2[c0] : 0.f);
            float bv1 = bias[c0 + 1] + (bias2 ? bias2[c0 + 1] : 0.f);
            float v[4] = {acc[mt][nt][0] + bv0, acc[mt][nt][1] + bv1,
                          acc[mt][nt][2] + bv0, acc[mt][nt][3] + bv1};
            int rr[4] = {r0, r0, r0 + 8, r0 + 8};
            int cc[4] = {c0, c0 + 1, c0, c0 + 1};
#pragma unroll
            for (int q = 0; q < 4; q++) {
                int m = rr[q], n = cc[q];
                float x = v[q];
                if (Cf) Cf[(size_t)m * N + n] = x;
                if (C3) {
                    bf16 h = __float2bfloat16(x);
                    bf16 l = __float2bfloat16(x - __bfloat162float(h));
                    size_t base = (size_t)m * 3 * C3K;
                    C3[base + n] = h; C3[base + C3K + n] = h; C3[base + 2 * C3K + n] = l;
                }
                if (Cscat) {
                    int t = m >> 4, bb_ = m & 15;
                    Cscat[((bb_ << 5) + t) * 1024 + n] = x;
                }
            }
        }
}

// ---------------- LSTM step (validated R3 version) ----------------
__global__ __launch_bounds__(256) void k_lstm_step(
    const float* __restrict__ Whh_f, const float* __restrict__ Whh_b, int s)
{
    __shared__ float sbuf[8192];
    int dir = blockIdx.x & 1;
    int h0 = (blockIdx.x >> 1) << 5;
    int t = dir ? (31 - s) : s;
    const float* __restrict__ Whh = dir ? Whh_b : Whh_f;
    int tid = threadIdx.x;
    {
        const float4* hp4 = (const float4*)(g_hT[s & 1] + dir * 8192);
        float4* sb4 = (float4*)sbuf;
#pragma unroll
        for (int i = 0; i < 8; i++) sb4[tid + i * 256] = hp4[tid + i * 256];
    }
    __syncthreads();
    int kq = tid >> 6;
    int sub = tid & 63;
    int gate = sub >> 4;
    int hg = sub & 15;
    int h = h0 + (hg << 1);
    const float* wr0 = Whh + (size_t)(gate * 512 + h) * 512 + (kq << 7);
    const float* wr1 = wr0 + 512;
    unsigned long long acc[2][8];
#pragma unroll
    for (int p = 0; p < 2; p++)
#pragma unroll
        for (int j = 0; j < 8; j++) acc[p][j] = 0ull;

    for (int k4 = 0; k4 < 128; k4 += 4) {
        float4 wa = *(const float4*)(wr0 + k4);
        float4 wb = *(const float4*)(wr1 + k4);
        float wav[4] = {wa.x, wa.y, wa.z, wa.w};
        float wbv[4] = {wb.x, wb.y, wb.z, wb.w};
#pragma unroll
        for (int j = 0; j < 4; j++) {
            int k = (kq << 7) + k4 + j;
            unsigned long long w2a = pk(wav[j], wav[j]);
            unsigned long long w2b = pk(wbv[j], wbv[j]);
            const ulonglong2* hb = (const ulonglong2*)&sbuf[k << 4];
            ulonglong2 q0 = hb[0], q1 = hb[1], q2 = hb[2], q3 = hb[3];
            fma2(acc[0][0], w2a, q0.x); fma2(acc[0][1], w2a, q0.y);
            fma2(acc[0][2], w2a, q1.x); fma2(acc[0][3], w2a, q1.y);
            fma2(acc[0][4], w2a, q2.x); fma2(acc[0][5], w2a, q2.y);
            fma2(acc[0][6], w2a, q3.x); fma2(acc[0][7], w2a, q3.y);
            fma2(acc[1][0], w2b, q0.x); fma2(acc[1][1], w2b, q0.y);
            fma2(acc[1][2], w2b, q1.x); fma2(acc[1][3], w2b, q1.y);
            fma2(acc[1][4], w2b, q2.x); fma2(acc[1][5], w2b, q2.y);
            fma2(acc[1][6], w2b, q3.x); fma2(acc[1][7], w2b, q3.y);
        }
    }
    __syncthreads();
#pragma unroll
    for (int p = 0; p < 2; p++)
#pragma unroll
        for (int j = 0; j < 8; j++) {
            float2 v = upk(acc[p][j]);
            int base = ((((kq << 2) + gate) * 16 + hg) * 2 + p) * 16 + (j << 1);
            sbuf[base] = v.x;
            sbuf[base + 1] = v.y;
        }
    __syncthreads();
    const float* gx = g_gx + ((size_t)dir * 512 + t * 16) * 2048;
    float* hNext = g_hT[(s + 1) & 1];
    for (int it = tid; it < 512; it += 256) {
        int hloc = it >> 4, b = it & 15;
        int hgl = hloc >> 1, p = hloc & 1;
        float v[4];
#pragma unroll
        for (int g = 0; g < 4; g++) {
            int bi = ((g * 16 + hgl) * 2 + p) * 16 + b;
            v[g] = sbuf[bi] + sbuf[bi + 2048] + sbuf[bi + 4096] + sbuf[bi + 6144]
                 + gx[(size_t)b * 2048 + g * 512 + h0 + hloc];
        }
        float i_ = 1.f / (1.f + expf(-v[0]));
        float f_ = 1.f / (1.f + expf(-v[1]));
        float gg = tanhf(v[2]);
        float o_ = 1.f / (1.f + expf(-v[3]));
        int hh = h0 + hloc;
        int ci = dir * 8192 + hh * 16 + b;
        float c = f_ * g_cT[ci] + i_ * gg;
        g_cT[ci] = c;
        float hn = o_ * tanhf(c);
        hNext[ci] = hn;
        g_hseq[(t * 16 + b) * 1024 + dir * 512 + hh] = hn;
    }
}

// ---------------- attention (validated R3 version) ----------------
__global__ __launch_bounds__(256) void k_att(
    const float* __restrict__ w_att, const float* __restrict__ b_att, float* __restrict__ out)
{
    __shared__ float hv[512], wv[512], sc[256], red[256];
    int b = blockIdx.x & 15, t = blockIdx.x >> 4;
    int tid = threadIdx.x;
    hv[tid] = g_hemA[(t * 16 + b) * 512 + tid];
    hv[tid + 256] = g_hemA[(t * 16 + b) * 512 + tid + 256];
    wv[tid] = w_att[tid];
    wv[tid + 256] = w_att[tid + 256];
    __syncthreads();
    int lane = tid & 31, wrp = tid >> 5;
    const float* xb = g_xt + (size_t)b * 256 * 512;
    float batt = b_att[0];
    for (int hw = wrp; hw < 256; hw += 8) {
        const float* xr = xb + hw * 512;
        float sum = 0.f;
        for (int e = lane; e < 512; e += 32) sum += wv[e] * tanh_fast(xr[e] + hv[e]);
#pragma unroll
        for (int o = 16; o; o >>= 1) sum += __shfl_xor_sync(0xffffffffu, sum, o);
        if (lane == 0) sc[hw] = sum + batt;
    }
    __syncthreads();
    float sv = sc[tid];
    red[tid] = sv;
    __syncthreads();
    for (int st = 128; st; st >>= 1) {
        if (tid < st) red[tid] = fmaxf(red[tid], red[tid + st]);
        __syncthreads();
    }
    float mx = red[0];
    __syncthreads();
    float e = expf(sv - mx);
    red[tid] = e;
    __syncthreads();
    for (int st = 128; st; st >>= 1) {
        if (tid < st) red[tid] += red[tid + st];
        __syncthreads();
    }
    float inv = 1.f / red[0];
    sc[tid] = e * inv;
    __syncthreads();
    float a0 = 0.f, a1 = 0.f;
    for (int hw = 0; hw < 256; hw++) {
        float al = sc[hw];
        const float* xr = xb + hw * 512;
        a0 += al * xr[tid];
        a1 += al * xr[tid + 256];
    }
    float* orow = out + (size_t)((b << 5) + t) * 1024 + 512;
    orow[tid] = a0;
    orow[tid + 256] = a1;
}

// ---------------- launch ----------------
extern "C" void kernel_launch(void* const* d_in, const int* in_sizes, int n_in,
                              void* d_out, int out_size) {
    const float* hidden_en = (const float*)d_in[0];
    const float* conv_f = (const float*)d_in[1];
    const float* W_ih_f = (const float*)d_in[2];
    const float* W_hh_f = (const float*)d_in[3];
    const float* b_ih_f = (const float*)d_in[4];
    const float* b_hh_f = (const float*)d_in[5];
    const float* W_ih_b = (const float*)d_in[6];
    const float* W_hh_b = (const float*)d_in[7];
    const float* b_ih_b = (const float*)d_in[8];
    const float* b_hh_b = (const float*)d_in[9];
    const float* W_dec = (const float*)d_in[10];
    const float* b_dec = (const float*)d_in[11];
    const float* W_em = (const float*)d_in[12];
    const float* b_em = (const float*)d_in[13];
    const float* W_hem = (const float*)d_in[14];
    const float* b_hem = (const float*)d_in[15];
    const float* w_att = (const float*)d_in[16];
    const float* b_att = (const float*)d_in[17];
    float* out = (float*)d_out;

#define SYM(p, s) void* p; cudaGetSymbolAddress(&p, s)
    SYM(p_gx, g_gx); SYM(p_xt, g_xt); SYM(p_hseq, g_hseq); SYM(p_hem, g_hemA);
    SYM(p_col3, g_col3); SYM(p_wem3, g_wem3); SYM(p_en3, g_en3);
    SYM(p_wf3, g_wihf3); SYM(p_wb3, g_wihb3);
    SYM(p_wd3, g_wdec3); SYM(p_wh3, g_whem3);
    SYM(p_hs3, g_hseq3); SYM(p_hd3, g_hde3);

    k_zero<<<64, 256>>>();
    k_im2col3<<<(4096 * 4608) / 256, 256>>>(conv_f);
    k_cvtB3<<<(512 * 4608) / 256, 256>>>(W_em, (bf16*)p_wem3, 4608, 512 * 4608);
    k_cvtA3<<<(512 * 512) / 256, 256>>>(hidden_en, (bf16*)p_en3, 512, 512 * 512);
    k_cvtB3<<<(2048 * 512) / 256, 256>>>(W_ih_f, (bf16*)p_wf3, 512, 2048 * 512);
    k_cvtB3<<<(2048 * 512) / 256, 256>>>(W_ih_b, (bf16*)p_wb3, 512, 2048 * 512);
    k_cvtB3<<<(512 * 1024) / 256, 256>>>(W_dec, (bf16*)p_wd3, 1024, 512 * 1024);
    k_cvtB3<<<(512 * 512) / 256, 256>>>(W_hem, (bf16*)p_wh3, 512, 512 * 512);

    // conv GEMM -> g_xt (M=4096, N=512, K3=13824)
    k_mma_gemm<<<dim3(4, 32), 256>>>((bf16*)p_col3, (bf16*)p_wem3, b_em, nullptr,
                                     (float*)p_xt, nullptr, 0, nullptr, 512, 13824);
    // input projections (M=512, N=2048, K3=1536)
    k_mma_gemm<<<dim3(16, 4), 256>>>((bf16*)p_en3, (bf16*)p_wf3, b_ih_f, b_hh_f,
                                     (float*)p_gx, nullptr, 0, nullptr, 2048, 1536);
    k_mma_gemm<<<dim3(16, 4), 256>>>((bf16*)p_en3, (bf16*)p_wb3, b_ih_b, b_hh_b,
                                     (float*)p_gx + 512 * 2048, nullptr, 0, nullptr, 2048, 1536);

    for (int s = 0; s < 32; s++) k_lstm_step<<<32, 256>>>(W_hh_f, W_hh_b, s);

    k_cvtA3<<<(512 * 1024) / 256, 256>>>((float*)p_hseq, (bf16*)p_hs3, 1024, 512 * 1024);
    // dec (M=512, N=512, K3=3072): scatter hidden_de into out + triple hde
    k_mma_gemm<<<dim3(4, 4), 256>>>((bf16*)p_hs3, (bf16*)p_wd3, b_dec, nullptr,
                                    nullptr, (bf16*)p_hd3, 512, out, 512, 3072);
    // hem (M=512, N=512, K3=1536)
    k_mma_gemm<<<dim3(4, 4), 256>>>((bf16*)p_hd3, (bf16*)p_wh3, b_hem, nullptr,
                                    (float*)p_hem, nullptr, 0, nullptr, 512, 1536);

    k_att<<<512, 256>>>(w_att, b_att, out);
}

// round 8
// speedup vs baseline: 1.9553x; 1.1045x over previous
#include <cuda_runtime.h>
#include <cuda_bf16.h>
#include <math.h>
#include <stdint.h>

typedef __nv_bfloat16 bf16;

// ---------------- scratch ----------------
__device__ float g_hT[2][16384];
__device__ float g_cT[16384];
__device__ float g_hseq[512 * 1024];
__device__ float g_gx[2 * 512 * 2048];
__device__ float g_hemA[512 * 512];
__device__ float g_xt[4096 * 512];
__device__ bf16 g_col2[4096u * 9216u];          // [hi(4608) | lo(4608)]
__device__ bf16 g_wem2[512 * 9216];
__device__ bf16 g_en2[512 * 1024];
__device__ bf16 g_wihf2[2048 * 1024], g_wihb2[2048 * 1024];
__device__ bf16 g_wdec2[512 * 2048];
__device__ bf16 g_whem2[512 * 1024];
__device__ bf16 g_hseq2[512 * 2048];
__device__ bf16 g_hde2[512 * 1024];

// ---------------- helpers ----------------
__device__ __forceinline__ void fma2(unsigned long long& d, unsigned long long a, unsigned long long b) {
    asm("fma.rn.f32x2 %0, %1, %2, %0;" : "+l"(d) : "l"(a), "l"(b));
}
__device__ __forceinline__ unsigned long long pk(float lo, float hi) {
    unsigned long long r;
    asm("mov.b64 %0, {%1, %2};" : "=l"(r) : "f"(lo), "f"(hi));
    return r;
}
__device__ __forceinline__ float2 upk(unsigned long long v) {
    float2 f;
    asm("mov.b64 {%0, %1}, %2;" : "=f"(f.x), "=f"(f.y) : "l"(v));
    return f;
}
__device__ __forceinline__ float tanh_fast(float x) {
    float y;
    asm("tanh.approx.f32 %0, %1;" : "=f"(y) : "f"(x));
    return y;
}
__device__ __forceinline__ uint32_t smem_u32(const void* p) {
    uint32_t a;
    asm("{ .reg .u64 t; cvta.to.shared.u64 t, %1; cvt.u32.u64 %0, t; }" : "=r"(a) : "l"(p));
    return a;
}

// ---------------- init & converts ----------------
__global__ void k_zero() {
    int i = blockIdx.x * 256 + threadIdx.x;
    g_hT[0][i] = 0.f;
    g_cT[i] = 0.f;
}
// [hi | lo] split layout, row-major, row stride 2K
__global__ void k_cvt2(const float* __restrict__ s, bf16* __restrict__ d, int K, int n) {
    int i = blockIdx.x * 256 + threadIdx.x;
    if (i >= n) return;
    int m = i / K, k = i % K;
    float v = s[i];
    bf16 h = __float2bfloat16(v);
    bf16 l = __float2bfloat16(v - __bfloat162float(h));
    size_t base = (size_t)m * 2 * K;
    d[base + k] = h;
    d[base + K + k] = l;
}
// im2col -> [hi|lo], K=4608
__global__ void k_im2col2(const float* __restrict__ cf) {
    int idx = blockIdx.x * 256 + threadIdx.x;   // < 4096*4608
    int k = idx % 4608, m = idx / 4608;
    int kw = k % 3, kh = (k / 3) % 3, c = k / 9;
    int w = m & 31, h = (m >> 5) & 7, b = m >> 8;
    int ih = h + kh - 1, iw = w + kw - 1;
    float v = 0.f;
    if (ih >= 0 && ih < 8 && iw >= 0 && iw < 32) v = cf[((b * 512 + c) * 8 + ih) * 32 + iw];
    bf16 hv = __float2bfloat16(v);
    size_t base = (size_t)m * 9216;
    g_col2[base + k] = hv;
    g_col2[base + 4608 + k] = __float2bfloat16(v - __bfloat162float(hv));
}

// ---------------- HMMA bf16 NT GEMM, cp.async double-buffered ----------------
// Storage [hi|lo] (2K); 3 phases: hi*hi, hi*lo, lo*hi. CTA tile 128x128, chunk 32.
#define PAD 40
#define TSZ (128 * PAD)
__device__ __forceinline__ void ld_chunk(uint32_t ds, const bf16* __restrict__ src,
                                         int row0, int rs, int koff, int tid) {
#pragma unroll
    for (int j = 0; j < 2; j++) {
        int ch = tid + (j << 8);
        int row = ch >> 2, c = ch & 3;
        const void* g = src + (size_t)(row0 + row) * rs + koff + (c << 3);
        uint32_t d = ds + (row * PAD + (c << 3)) * 2;
        asm volatile("cp.async.ca.shared.global [%0], [%1], 16;" :: "r"(d), "l"(g) : "memory");
    }
}

__global__ __launch_bounds__(256) void k_mma_gemm(
    const bf16* __restrict__ A2, const bf16* __restrict__ B2,
    const float* __restrict__ bias, const float* __restrict__ bias2,
    float* __restrict__ Cf, bf16* __restrict__ C2, int C2K,
    float* __restrict__ Cscat, int N, int K)
{
    __shared__ __align__(16) bf16 As[2][TSZ];
    __shared__ __align__(16) bf16 Bs[2][TSZ];
    int tid = threadIdx.x, lane = tid & 31, wid = tid >> 5;
    int g = lane >> 2, t2 = (lane & 3) << 1;
    int bm = blockIdx.y << 7, bn = blockIdx.x << 7;
    int wm = (wid >> 1) << 5, wn = (wid & 1) << 6;
    uint32_t asb = smem_u32(As), bsb = smem_u32(Bs);
    int rs = K << 1;                         // row stride in elems
    int KC = K >> 5, S = KC * 3;
    float acc[2][8][4];
#pragma unroll
    for (int mt = 0; mt < 2; mt++)
#pragma unroll
        for (int nt = 0; nt < 8; nt++)
#pragma unroll
            for (int q = 0; q < 4; q++) acc[mt][nt][q] = 0.f;

    // prologue: chunk 0 (phase 0: hi*hi)
    ld_chunk(asb, A2, bm, rs, 0, tid);
    ld_chunk(bsb, B2, bn, rs, 0, tid);
    asm volatile("cp.async.commit_group;" ::: "memory");

    for (int s = 0; s < S; s++) {
        int cur = s & 1;
        if (s + 1 < S) {
            int s1 = s + 1;
            int p = s1 / KC, cc = s1 - p * KC;
            int aoff = ((p == 2) ? K : 0) + (cc << 5);
            int boff = ((p == 1) ? K : 0) + (cc << 5);
            uint32_t nb = (uint32_t)((cur ^ 1) * TSZ * 2);
            ld_chunk(asb + nb, A2, bm, rs, aoff, tid);
            ld_chunk(bsb + nb, B2, bn, rs, boff, tid);
            asm volatile("cp.async.commit_group;" ::: "memory");
            asm volatile("cp.async.wait_group 1;" ::: "memory");
        } else {
            asm volatile("cp.async.wait_group 0;" ::: "memory");
        }
        __syncthreads();
        const bf16* Asc = As[cur];
        const bf16* Bsc = Bs[cur];
#pragma unroll
        for (int kk = 0; kk < 2; kk++) {
            int kb = kk << 4;
            uint32_t a[2][4], b[8][2];
#pragma unroll
            for (int mt = 0; mt < 2; mt++) {
                const bf16* ab = &Asc[(wm + (mt << 4) + g) * PAD + kb + t2];
                a[mt][0] = *(const uint32_t*)ab;
                a[mt][1] = *(const uint32_t*)(ab + 8 * PAD);
                a[mt][2] = *(const uint32_t*)(ab + 8);
                a[mt][3] = *(const uint32_t*)(ab + 8 * PAD + 8);
            }
#pragma unroll
            for (int nt = 0; nt < 8; nt++) {
                const bf16* bb = &Bsc[(wn + (nt << 3) + g) * PAD + kb + t2];
                b[nt][0] = *(const uint32_t*)bb;
                b[nt][1] = *(const uint32_t*)(bb + 8);
            }
#pragma unroll
            for (int mt = 0; mt < 2; mt++)
#pragma unroll
                for (int nt = 0; nt < 8; nt++)
                    asm volatile(
                        "mma.sync.aligned.m16n8k16.row.col.f32.bf16.bf16.f32 "
                        "{%0,%1,%2,%3},{%4,%5,%6,%7},{%8,%9},{%0,%1,%2,%3};"
                        : "+f"(acc[mt][nt][0]), "+f"(acc[mt][nt][1]),
                          "+f"(acc[mt][nt][2]), "+f"(acc[mt][nt][3])
                        : "r"(a[mt][0]), "r"(a[mt][1]), "r"(a[mt][2]), "r"(a[mt][3]),
                          "r"(b[nt][0]), "r"(b[nt][1]));
        }
        __syncthreads();
    }
#pragma unroll
    for (int mt = 0; mt < 2; mt++)
#pragma unroll
        for (int nt = 0; nt < 8; nt++) {
            int r0 = bm + wm + (mt << 4) + g;
            int c0 = bn + wn + (nt << 3) + t2;
            float bv0 = bias[c0] + (bias2 ? bias2[c0] : 0.f);
            float bv1 = bias[c0 + 1] + (bias2 ? bias2[c0 + 1] : 0.f);
            float v[4] = {acc[mt][nt][0] + bv0, acc[mt][nt][1] + bv1,
                          acc[mt][nt][2] + bv0, acc[mt][nt][3] + bv1};
            int rr[4] = {r0, r0, r0 + 8, r0 + 8};
            int cc[4] = {c0, c0 + 1, c0, c0 + 1};
#pragma unroll
            for (int q = 0; q < 4; q++) {
                int m = rr[q], n = cc[q];
                float x = v[q];
                if (Cf) Cf[(size_t)m * N + n] = x;
                if (C2) {
                    bf16 h = __float2bfloat16(x);
                    size_t base = (size_t)m * 2 * C2K;
                    C2[base + n] = h;
                    C2[base + C2K + n] = __float2bfloat16(x - __bfloat162float(h));
                }
                if (Cscat) {
                    int t = m >> 4, bb_ = m & 15;
                    Cscat[((bb_ << 5) + t) * 1024 + n] = x;
                }
            }
        }
}

// ---------------- LSTM step (validated) ----------------
__global__ __launch_bounds__(256) void k_lstm_step(
    const float* __restrict__ Whh_f, const float* __restrict__ Whh_b, int s)
{
    __shared__ float sbuf[8192];
    int dir = blockIdx.x & 1;
    int h0 = (blockIdx.x >> 1) << 5;
    int t = dir ? (31 - s) : s;
    const float* __restrict__ Whh = dir ? Whh_b : Whh_f;
    int tid = threadIdx.x;
    {
        const float4* hp4 = (const float4*)(g_hT[s & 1] + dir * 8192);
        float4* sb4 = (float4*)sbuf;
#pragma unroll
        for (int i = 0; i < 8; i++) sb4[tid + i * 256] = hp4[tid + i * 256];
    }
    __syncthreads();
    int kq = tid >> 6;
    int sub = tid & 63;
    int gate = sub >> 4;
    int hg = sub & 15;
    int h = h0 + (hg << 1);
    const float* wr0 = Whh + (size_t)(gate * 512 + h) * 512 + (kq << 7);
    const float* wr1 = wr0 + 512;
    unsigned long long acc[2][8];
#pragma unroll
    for (int p = 0; p < 2; p++)
#pragma unroll
        for (int j = 0; j < 8; j++) acc[p][j] = 0ull;

    for (int k4 = 0; k4 < 128; k4 += 4) {
        float4 wa = *(const float4*)(wr0 + k4);
        float4 wb = *(const float4*)(wr1 + k4);
        float wav[4] = {wa.x, wa.y, wa.z, wa.w};
        float wbv[4] = {wb.x, wb.y, wb.z, wb.w};
#pragma unroll
        for (int j = 0; j < 4; j++) {
            int k = (kq << 7) + k4 + j;
            unsigned long long w2a = pk(wav[j], wav[j]);
            unsigned long long w2b = pk(wbv[j], wbv[j]);
            const ulonglong2* hb = (const ulonglong2*)&sbuf[k << 4];
            ulonglong2 q0 = hb[0], q1 = hb[1], q2 = hb[2], q3 = hb[3];
            fma2(acc[0][0], w2a, q0.x); fma2(acc[0][1], w2a, q0.y);
            fma2(acc[0][2], w2a, q1.x); fma2(acc[0][3], w2a, q1.y);
            fma2(acc[0][4], w2a, q2.x); fma2(acc[0][5], w2a, q2.y);
            fma2(acc[0][6], w2a, q3.x); fma2(acc[0][7], w2a, q3.y);
            fma2(acc[1][0], w2b, q0.x); fma2(acc[1][1], w2b, q0.y);
            fma2(acc[1][2], w2b, q1.x); fma2(acc[1][3], w2b, q1.y);
            fma2(acc[1][4], w2b, q2.x); fma2(acc[1][5], w2b, q2.y);
            fma2(acc[1][6], w2b, q3.x); fma2(acc[1][7], w2b, q3.y);
        }
    }
    __syncthreads();
#pragma unroll
    for (int p = 0; p < 2; p++)
#pragma unroll
        for (int j = 0; j < 8; j++) {
            float2 v = upk(acc[p][j]);
            int base = ((((kq << 2) + gate) * 16 + hg) * 2 + p) * 16 + (j << 1);
            sbuf[base] = v.x;
            sbuf[base + 1] = v.y;
        }
    __syncthreads();
    const float* gx = g_gx + ((size_t)dir * 512 + t * 16) * 2048;
    float* hNext = g_hT[(s + 1) & 1];
    for (int it = tid; it < 512; it += 256) {
        int hloc = it >> 4, b = it & 15;
        int hgl = hloc >> 1, p = hloc & 1;
        float v[4];
#pragma unroll
        for (int g2 = 0; g2 < 4; g2++) {
            int bi = ((g2 * 16 + hgl) * 2 + p) * 16 + b;
            v[g2] = sbuf[bi] + sbuf[bi + 2048] + sbuf[bi + 4096] + sbuf[bi + 6144]
                  + gx[(size_t)b * 2048 + g2 * 512 + h0 + hloc];
        }
        float i_ = 1.f / (1.f + expf(-v[0]));
        float f_ = 1.f / (1.f + expf(-v[1]));
        float gg = tanhf(v[2]);
        float o_ = 1.f / (1.f + expf(-v[3]));
        int hh = h0 + hloc;
        int ci = dir * 8192 + hh * 16 + b;
        float c = f_ * g_cT[ci] + i_ * gg;
        g_cT[ci] = c;
        float hn = o_ * tanhf(c);
        hNext[ci] = hn;
        g_hseq[(t * 16 + b) * 1024 + dir * 512 + hh] = hn;
    }
}

// ---------------- attention (validated) ----------------
__global__ __launch_bounds__(256) void k_att(
    const float* __restrict__ w_att, const float* __restrict__ b_att, float* __restrict__ out)
{
    __shared__ float hv[512], wv[512], sc[256], red[256];
    int b = blockIdx.x & 15, t = blockIdx.x >> 4;
    int tid = threadIdx.x;
    hv[tid] = g_hemA[(t * 16 + b) * 512 + tid];
    hv[tid + 256] = g_hemA[(t * 16 + b) * 512 + tid + 256];
    wv[tid] = w_att[tid];
    wv[tid + 256] = w_att[tid + 256];
    __syncthreads();
    int lane = tid & 31, wrp = tid >> 5;
    const float* xb = g_xt + (size_t)b * 256 * 512;
    float batt = b_att[0];
    for (int hw = wrp; hw < 256; hw += 8) {
        const float* xr = xb + hw * 512;
        float sum = 0.f;
        for (int e = lane; e < 512; e += 32) sum += wv[e] * tanh_fast(xr[e] + hv[e]);
#pragma unroll
        for (int o = 16; o; o >>= 1) sum += __shfl_xor_sync(0xffffffffu, sum, o);
        if (lane == 0) sc[hw] = sum + batt;
    }
    __syncthreads();
    float sv = sc[tid];
    red[tid] = sv;
    __syncthreads();
    for (int st = 128; st; st >>= 1) {
        if (tid < st) red[tid] = fmaxf(red[tid], red[tid + st]);
        __syncthreads();
    }
    float mx = red[0];
    __syncthreads();
    float e = expf(sv - mx);
    red[tid] = e;
    __syncthreads();
    for (int st = 128; st; st >>= 1) {
        if (tid < st) red[tid] += red[tid + st];
        __syncthreads();
    }
    float inv = 1.f / red[0];
    sc[tid] = e * inv;
    __syncthreads();
    float a0 = 0.f, a1 = 0.f;
    for (int hw = 0; hw < 256; hw++) {
        float al = sc[hw];
        const float* xr = xb + hw * 512;
        a0 += al * xr[tid];
        a1 += al * xr[tid + 256];
    }
    float* orow = out + (size_t)((b << 5) + t) * 1024 + 512;
    orow[tid] = a0;
    orow[tid + 256] = a1;
}

// ---------------- launch ----------------
extern "C" void kernel_launch(void* const* d_in, const int* in_sizes, int n_in,
                              void* d_out, int out_size) {
    const float* hidden_en = (const float*)d_in[0];
    const float* conv_f = (const float*)d_in[1];
    const float* W_ih_f = (const float*)d_in[2];
    const float* W_hh_f = (const float*)d_in[3];
    const float* b_ih_f = (const float*)d_in[4];
    const float* b_hh_f = (const float*)d_in[5];
    const float* W_ih_b = (const float*)d_in[6];
    const float* W_hh_b = (const float*)d_in[7];
    const float* b_ih_b = (const float*)d_in[8];
    const float* b_hh_b = (const float*)d_in[9];
    const float* W_dec = (const float*)d_in[10];
    const float* b_dec = (const float*)d_in[11];
    const float* W_em = (const float*)d_in[12];
    const float* b_em = (const float*)d_in[13];
    const float* W_hem = (const float*)d_in[14];
    const float* b_hem = (const float*)d_in[15];
    const float* w_att = (const float*)d_in[16];
    const float* b_att = (const float*)d_in[17];
    float* out = (float*)d_out;

#define SYM(p, s) void* p; cudaGetSymbolAddress(&p, s)
    SYM(p_gx, g_gx); SYM(p_xt, g_xt); SYM(p_hseq, g_hseq); SYM(p_hem, g_hemA);
    SYM(p_col2, g_col2); SYM(p_wem2, g_wem2); SYM(p_en2, g_en2);
    SYM(p_wf2, g_wihf2); SYM(p_wb2, g_wihb2);
    SYM(p_wd2, g_wdec2); SYM(p_wh2, g_whem2);
    SYM(p_hs2, g_hseq2); SYM(p_hd2, g_hde2);

    k_zero<<<64, 256>>>();
    k_im2col2<<<(4096 * 4608) / 256, 256>>>(conv_f);
    k_cvt2<<<(512 * 4608) / 256, 256>>>(W_em, (bf16*)p_wem2, 4608, 512 * 4608);
    k_cvt2<<<(512 * 512) / 256, 256>>>(hidden_en, (bf16*)p_en2, 512, 512 * 512);
    k_cvt2<<<(2048 * 512) / 256, 256>>>(W_ih_f, (bf16*)p_wf2, 512, 2048 * 512);
    k_cvt2<<<(2048 * 512) / 256, 256>>>(W_ih_b, (bf16*)p_wb2, 512, 2048 * 512);
    k_cvt2<<<(512 * 1024) / 256, 256>>>(W_dec, (bf16*)p_wd2, 1024, 512 * 1024);
    k_cvt2<<<(512 * 512) / 256, 256>>>(W_hem, (bf16*)p_wh2, 512, 512 * 512);

    // conv GEMM -> g_xt (M=4096, N=512, K=4608)
    k_mma_gemm<<<dim3(4, 32), 256>>>((bf16*)p_col2, (bf16*)p_wem2, b_em, nullptr,
                                     (float*)p_xt, nullptr, 0, nullptr, 512, 4608);
    // input projections (M=512, N=2048, K=512)
    k_mma_gemm<<<dim3(16, 4), 256>>>((bf16*)p_en2, (bf16*)p_wf2, b_ih_f, b_hh_f,
                                     (float*)p_gx, nullptr, 0, nullptr, 2048, 512);
    k_mma_gemm<<<dim3(16, 4), 256>>>((bf16*)p_en2, (bf16*)p_wb2, b_ih_b, b_hh_b,
                                     (float*)p_gx + 512 * 2048, nullptr, 0, nullptr, 2048, 512);

    for (int s = 0; s < 32; s++) k_lstm_step<<<32, 256>>>(W_hh_f, W_hh_b, s);

    k_cvt2<<<(512 * 1024) / 256, 256>>>((float*)p_hseq, (bf16*)p_hs2, 1024, 512 * 1024);
    // dec (M=512, N=512, K=1024): scatter hidden_de into out + [hi|lo] hde
    k_mma_gemm<<<dim3(4, 4), 256>>>((bf16*)p_hs2, (bf16*)p_wd2, b_dec, nullptr,
                                    nullptr, (bf16*)p_hd2, 512, out, 512, 1024);
    // hem (M=512, N=512, K=512)
    k_mma_gemm<<<dim3(4, 4), 256>>>((bf16*)p_hd2, (bf16*)p_wh2, b_hem, nullptr,
                                    (float*)p_hem, nullptr, 0, nullptr, 512, 512);

    k_att<<<512, 256>>>(w_att, b_att, out);
}